// round 14
// baseline (speedup 1.0000x reference)
#include <cuda_runtime.h>
#include <cuda_fp16.h>
#include <mma.h>
using namespace nvcuda;

#define NMAX   100000
#define EMAX   1600000
#define DDIM   64
#define NGR    64

// Scratch (static device globals; no allocation allowed)
__device__ float g_dis[NMAX];               // rsqrt(deg)
__device__ uint4 g_thA[NMAX * 8];           // fp16 messages, ping
__device__ uint4 g_thB[NMAX * 8];           // fp16 messages, pong
__device__ float g_agg[NMAX * DDIM];        // final-layer aggregation (fp32)
__device__ float g_pooled[NGR * DDIM];
__device__ int   g_hist[NMAX];              // in-degree histogram
__device__ int   g_off[NMAX + 1];           // CSR offsets (by dst)
__device__ int   g_cursor[NMAX];            // fill cursors
__device__ int   g_csr[EMAX];               // CSR src indices
__device__ int   g_bsum[128];               // scan block sums

// ---------------------------------------------------------------------------
// degree precompute
// ---------------------------------------------------------------------------
__global__ void k_zero_hist(int n) {
    int i = blockIdx.x * blockDim.x + threadIdx.x;
    if (i < n) g_hist[i] = 0;
}

__global__ void k_count(const int* __restrict__ dst, int E) {
    int e = blockIdx.x * blockDim.x + threadIdx.x;
    if (e < E) atomicAdd(&g_hist[dst[e]], 1);
}

// ---------------------------------------------------------------------------
// Scan level 1: per-1024 block exclusive scan; also g_dis = rsqrt(deg+1)
// ---------------------------------------------------------------------------
__global__ void __launch_bounds__(1024) k_scan1(int n) {
    __shared__ int sh[32];
    int i = blockIdx.x * 1024 + threadIdx.x;
    int lane = threadIdx.x & 31, w = threadIdx.x >> 5;
    int v = (i < n) ? g_hist[i] : 0;
    if (i < n) g_dis[i] = rsqrtf((float)(v + 1));   // fused norm
    int x = v;
    #pragma unroll
    for (int o = 1; o < 32; o <<= 1) {
        int y = __shfl_up_sync(~0u, x, o);
        if (lane >= o) x += y;
    }
    if (lane == 31) sh[w] = x;
    __syncthreads();
    if (threadIdx.x < 32) {
        int y = sh[threadIdx.x];
        #pragma unroll
        for (int o = 1; o < 32; o <<= 1) {
            int z = __shfl_up_sync(~0u, y, o);
            if (threadIdx.x >= o) y += z;
        }
        sh[threadIdx.x] = y;
    }
    __syncthreads();
    int base = (w > 0) ? sh[w - 1] : 0;
    int incl = x + base;
    if (i < n) g_off[i] = incl - v;          // exclusive within block
    if (threadIdx.x == 1023) g_bsum[blockIdx.x] = incl;
}

// ---------------------------------------------------------------------------
// Scan finalize: each block redundantly scans g_bsum; block 0 zeroes g_pooled.
// ---------------------------------------------------------------------------
__global__ void __launch_bounds__(256) k_scanfin(int n, int E, int nb) {
    __shared__ int boff[128];
    __shared__ int sh[4];
    int t = threadIdx.x;
    int lane = t & 31, w = t >> 5;

    if (blockIdx.x == 0) {
        #pragma unroll
        for (int q = 0; q < NGR * DDIM / 256; q++)
            g_pooled[q * 256 + t] = 0.0f;
    }

    int v = 0, x = 0;
    if (t < 128) {
        v = (t < nb) ? g_bsum[t] : 0;
        x = v;
        #pragma unroll
        for (int o = 1; o < 32; o <<= 1) {
            int y = __shfl_up_sync(~0u, x, o);
            if (lane >= o) x += y;
        }
        if (lane == 31) sh[w] = x;
    }
    __syncthreads();
    if (t < 4) {
        int y = sh[t];
        #pragma unroll
        for (int o = 1; o < 4; o <<= 1) {
            int z = __shfl_up_sync(0xF, y, o);
            if (t >= o) y += z;
        }
        sh[t] = y;
    }
    __syncthreads();
    if (t < 128) {
        int base = (w > 0) ? sh[w - 1] : 0;
        boff[t] = x + base - v;              // exclusive scan of block sums
    }
    __syncthreads();

    int i = blockIdx.x * 256 + t;
    if (i < n) {
        int o = g_off[i] + boff[i >> 10];
        g_off[i] = o;
        g_cursor[i] = o;
    }
    if (i == 0) g_off[n] = E;
}

__global__ void k_fill(const int* __restrict__ src, const int* __restrict__ dst, int E) {
    int e = blockIdx.x * blockDim.x + threadIdx.x;
    if (e < E) {
        int pos = atomicAdd(&g_cursor[dst[e]], 1);
        g_csr[pos] = src[e];
    }
}

// ---------------------------------------------------------------------------
// Shared wmma tile machinery
// ---------------------------------------------------------------------------
#define XS_LD 72
#define AC_LD 68
#define SM_XS_BYTES (128 * XS_LD * 2)            // 18432
#define SM_WS_BYTES (64 * XS_LD * 2)             //  9216
#define SM_ACC_BYTES (8 * 16 * AC_LD * 4)        // 34816
#define SM_TOTAL (SM_ACC_BYTES > (SM_XS_BYTES + SM_WS_BYTES) ? SM_ACC_BYTES : (SM_XS_BYTES + SM_WS_BYTES))

// wmma mainloop + fp16 epilogue (writes th_out with dis scaling).
// Requires xs/ws staged and __syncthreads() already done.
__device__ __forceinline__ void mma_and_epilogue(
    char* smbuf, uint4* __restrict__ th_out, int node0, int n, int tid)
{
    __half (*xs)[XS_LD] = reinterpret_cast<__half(*)[XS_LD]>(smbuf);
    __half (*ws)[XS_LD] = reinterpret_cast<__half(*)[XS_LD]>(smbuf + SM_XS_BYTES);
    int warp = tid >> 5;

    wmma::fragment<wmma::matrix_a, 16, 16, 16, __half, wmma::row_major> fa;
    wmma::fragment<wmma::matrix_b, 16, 16, 16, __half, wmma::row_major> fb;
    wmma::fragment<wmma::accumulator, 16, 16, 16, float> facc[4];
    #pragma unroll
    for (int n0 = 0; n0 < 4; n0++) wmma::fill_fragment(facc[n0], 0.0f);

    #pragma unroll
    for (int k0 = 0; k0 < 4; k0++) {
        wmma::load_matrix_sync(fa, &xs[warp * 16][k0 * 16], XS_LD);
        #pragma unroll
        for (int n0 = 0; n0 < 4; n0++) {
            wmma::load_matrix_sync(fb, &ws[k0 * 16][n0 * 16], XS_LD);
            wmma::mma_sync(facc[n0], fa, fb, facc[n0]);
        }
    }

    __syncthreads();   // everyone done reading xs/ws; reuse smem for acc

    float (*accb)[AC_LD] = reinterpret_cast<float(*)[AC_LD]>(smbuf + warp * 16 * AC_LD * 4);
    #pragma unroll
    for (int n0 = 0; n0 < 4; n0++)
        wmma::store_matrix_sync(&accb[0][n0 * 16], facc[n0], AC_LD, wmma::mem_row_major);
    __syncwarp();

    int lane = tid & 31;
    int row = lane >> 1;                 // 0..15
    int sbase = (lane & 1) * 4;          // uint4 slots [sbase, sbase+4)
    int nrow = node0 + warp * 16 + row;
    if (nrow < n) {
        float d = g_dis[nrow];
        #pragma unroll
        for (int s = 0; s < 4; s++) {
            int c0 = (sbase + s) * 8;
            __half2 h0 = __floats2half2_rn(accb[row][c0 + 0] * d, accb[row][c0 + 1] * d);
            __half2 h1 = __floats2half2_rn(accb[row][c0 + 2] * d, accb[row][c0 + 3] * d);
            __half2 h2 = __floats2half2_rn(accb[row][c0 + 4] * d, accb[row][c0 + 5] * d);
            __half2 h3 = __floats2half2_rn(accb[row][c0 + 6] * d, accb[row][c0 + 7] * d);
            uint4 u;
            u.x = *reinterpret_cast<unsigned*>(&h0);
            u.y = *reinterpret_cast<unsigned*>(&h1);
            u.z = *reinterpret_cast<unsigned*>(&h2);
            u.w = *reinterpret_cast<unsigned*>(&h3);
            th_out[nrow * 8 + sbase + s] = u;
        }
    }
}

// ---------------------------------------------------------------------------
// Layer-1 GEMM: stages x (fp32 input) -> fp16 tile -> wmma -> g_thA
// ---------------------------------------------------------------------------
__global__ void __launch_bounds__(256) k_gemm1(
    const float* __restrict__ in, const float* __restrict__ W, int n)
{
    __shared__ __align__(32) char smbuf[SM_TOTAL];
    __half (*xs)[XS_LD] = reinterpret_cast<__half(*)[XS_LD]>(smbuf);
    __half (*ws)[XS_LD] = reinterpret_cast<__half(*)[XS_LD]>(smbuf + SM_XS_BYTES);

    int tid = threadIdx.x;
    int node0 = blockIdx.x * 128;

    for (int idx = tid; idx < 64 * 64; idx += 256)
        ws[idx >> 6][idx & 63] = __float2half_rn(W[idx]);

    for (int idx = tid; idx < 128 * 64; idx += 256) {
        int r = idx >> 6, c = idx & 63;
        int nrow = node0 + r;
        float v = (nrow < n) ? in[nrow * 64 + c] : 0.0f;
        xs[r][c] = __float2half_rn(v);
    }
    __syncthreads();

    mma_and_epilogue(smbuf, g_thA, node0, n, tid);
}

// ---------------------------------------------------------------------------
// Fused agg + bias/relu + GEMM (layers 2,3):
//   aggval[i][c] = dis[i] * ( th_in[i][c] + sum_{j in CSR[i]} th_in[j][c] )
//   xs[i][c]     = fp16( relu(aggval + bprev[c]) )
//   th_out       = fp16( dis * (xs @ W) )
// Agg phase: 2 threads per node, 32 fp32 accumulators each.
// ---------------------------------------------------------------------------
__device__ __forceinline__ void addh8(float* acc, uint4 v) {
    const __half2* h = reinterpret_cast<const __half2*>(&v);
    float2 f0 = __half22float2(h[0]);
    float2 f1 = __half22float2(h[1]);
    float2 f2 = __half22float2(h[2]);
    float2 f3 = __half22float2(h[3]);
    acc[0] += f0.x; acc[1] += f0.y;
    acc[2] += f1.x; acc[3] += f1.y;
    acc[4] += f2.x; acc[5] += f2.y;
    acc[6] += f3.x; acc[7] += f3.y;
}

__global__ void __launch_bounds__(256) k_fused(
    const uint4* __restrict__ th_in, uint4* __restrict__ th_out,
    const float* __restrict__ W, const float* __restrict__ bprev, int n)
{
    __shared__ __align__(32) char smbuf[SM_TOTAL];
    __shared__ float bs[64];
    __half (*xs)[XS_LD] = reinterpret_cast<__half(*)[XS_LD]>(smbuf);
    __half (*ws)[XS_LD] = reinterpret_cast<__half(*)[XS_LD]>(smbuf + SM_XS_BYTES);

    int tid = threadIdx.x;
    int node0 = blockIdx.x * 128;

    for (int idx = tid; idx < 64 * 64; idx += 256)
        ws[idx >> 6][idx & 63] = __float2half_rn(W[idx]);
    if (tid < 64) bs[tid] = bprev[tid];

    // ---- agg phase: r = tid>>1 (node-in-tile), h = tid&1 (column half) ----
    int r = tid >> 1;
    int h = tid & 1;
    int node = node0 + r;

    float acc[32];
    #pragma unroll
    for (int q = 0; q < 32; q++) acc[q] = 0.0f;

    if (node < n) {
        int base = node * 8 + h * 4;
        #pragma unroll
        for (int q = 0; q < 4; q++)
            addh8(acc + q * 8, th_in[base + q]);   // self loop

        int beg = g_off[node];
        int end = g_off[node + 1];
        for (int j = beg; j < end; j++) {
            int sb = g_csr[j] * 8 + h * 4;
            uint4 v0 = th_in[sb + 0];
            uint4 v1 = th_in[sb + 1];
            uint4 v2 = th_in[sb + 2];
            uint4 v3 = th_in[sb + 3];
            addh8(acc + 0,  v0);
            addh8(acc + 8,  v1);
            addh8(acc + 16, v2);
            addh8(acc + 24, v3);
        }
        float d = g_dis[node];
        int cbase = h * 32;
        #pragma unroll
        for (int q = 0; q < 32; q += 2) {
            float a0 = fmaxf(acc[q]     * d + bs[cbase + q],     0.0f);
            float a1 = fmaxf(acc[q + 1] * d + bs[cbase + q + 1], 0.0f);
            __half2 hh = __floats2half2_rn(a0, a1);
            *reinterpret_cast<__half2*>(&xs[r][cbase + q]) = hh;
        }
    } else {
        int cbase = h * 32;
        #pragma unroll
        for (int q = 0; q < 32; q += 2)
            *reinterpret_cast<__half2*>(&xs[r][cbase + q]) = __floats2half2_rn(0.f, 0.f);
    }
    __syncthreads();

    mma_and_epilogue(smbuf, th_out, node0, n, tid);
}

// ---------------------------------------------------------------------------
// Final aggregation (layer 3 output): agg fp32 for pooling.
// 8 lanes per node. 4 nodes/warp, 32/block.
// ---------------------------------------------------------------------------
__global__ void __launch_bounds__(256) k_agg(const uint4* __restrict__ th_in, int n) {
    int tid = threadIdx.x;
    int lane = tid & 31;
    int warp = tid >> 5;
    int node = blockIdx.x * 32 + warp * 4 + (lane >> 3);
    int s = lane & 7;
    if (node >= n) return;

    float acc[8];
    #pragma unroll
    for (int q = 0; q < 8; q++) acc[q] = 0.0f;

    addh8(acc, th_in[node * 8 + s]);     // self loop

    int beg = g_off[node];
    int end = g_off[node + 1];
    int j = beg;
    for (; j + 4 <= end; j += 4) {
        int s0 = g_csr[j], s1 = g_csr[j + 1], s2 = g_csr[j + 2], s3 = g_csr[j + 3];
        uint4 v0 = th_in[s0 * 8 + s];
        uint4 v1 = th_in[s1 * 8 + s];
        uint4 v2 = th_in[s2 * 8 + s];
        uint4 v3 = th_in[s3 * 8 + s];
        addh8(acc, v0); addh8(acc, v1); addh8(acc, v2); addh8(acc, v3);
    }
    for (; j < end; j++)
        addh8(acc, th_in[g_csr[j] * 8 + s]);

    float d = g_dis[node];
    float4 o0 = make_float4(acc[0] * d, acc[1] * d, acc[2] * d, acc[3] * d);
    float4 o1 = make_float4(acc[4] * d, acc[5] * d, acc[6] * d, acc[7] * d);
    float4* out = reinterpret_cast<float4*>(&g_agg[node * 64 + s * 8]);
    out[0] = o0;
    out[1] = o1;
}

// ---------------------------------------------------------------------------
// Pool: pooled[batch[i]] += relu(agg[i] + b3); batch sorted -> run-length.
// ---------------------------------------------------------------------------
__device__ __forceinline__ void pool_flush(int gph, int s, float4 sum) {
    float* p = &g_pooled[gph * 64 + s * 4];
    asm volatile("red.global.add.v4.f32 [%0], {%1,%2,%3,%4};"
                 :: "l"(p), "f"(sum.x), "f"(sum.y), "f"(sum.z), "f"(sum.w)
                 : "memory");
}

__global__ void k_pool(const int* __restrict__ batch, const float* __restrict__ b3, int n) {
    int tid = threadIdx.x;
    int s = tid & 15;
    int chunk = tid >> 4;
    int n0 = blockIdx.x * 256 + chunk * 16;
    float4 b4 = reinterpret_cast<const float4*>(b3)[s];

    float4 sum = make_float4(0.f, 0.f, 0.f, 0.f);
    int cur = -1;
    for (int j = 0; j < 16; j++) {
        int nn = n0 + j;
        if (nn >= n) break;
        int gph = batch[nn];
        if (gph != cur) {
            if (cur >= 0) pool_flush(cur, s, sum);
            cur = gph;
            sum = make_float4(0.f, 0.f, 0.f, 0.f);
        }
        float4 v = reinterpret_cast<const float4*>(g_agg)[nn * 16 + s];
        sum.x += fmaxf(v.x + b4.x, 0.0f);
        sum.y += fmaxf(v.y + b4.y, 0.0f);
        sum.z += fmaxf(v.z + b4.z, 0.0f);
        sum.w += fmaxf(v.w + b4.w, 0.0f);
    }
    if (cur >= 0) pool_flush(cur, s, sum);
}

__global__ void k_final(const float* __restrict__ lw, const float* __restrict__ lb,
                        float* __restrict__ out) {
    int g = threadIdx.x;   // 64 threads
    float s = lb[0];
    #pragma unroll
    for (int c = 0; c < 64; c++)
        s += g_pooled[g * 64 + c] * lw[c];
    out[g] = s;
}

// ---------------------------------------------------------------------------
extern "C" void kernel_launch(void* const* d_in, const int* in_sizes, int n_in,
                              void* d_out, int out_size) {
    const float* x  = (const float*)d_in[0];
    const int*   ei = (const int*)  d_in[1];
    const int*   batch = (const int*)d_in[2];
    const float* W1 = (const float*)d_in[3];
    const float* b1 = (const float*)d_in[4];
    const float* W2 = (const float*)d_in[5];
    const float* b2 = (const float*)d_in[6];
    const float* W3 = (const float*)d_in[7];
    const float* b3 = (const float*)d_in[8];
    const float* lw = (const float*)d_in[9];
    const float* lb = (const float*)d_in[10];
    float* out = (float*)d_out;

    int n = in_sizes[0] / DDIM;
    int E = in_sizes[1] / 2;
    const int* src = ei;
    const int* dst = ei + E;

    // degree + normalization + CSR build (scanfin also zeroes g_pooled)
    k_zero_hist<<<(n + 255) / 256, 256>>>(n);
    k_count<<<(E + 255) / 256, 256>>>(dst, E);
    int nb = (n + 1023) / 1024;
    k_scan1<<<nb, 1024>>>(n);
    k_scanfin<<<(n + 255) / 256, 256>>>(n, E, nb);
    k_fill<<<(E + 255) / 256, 256>>>(src, dst, E);

    int gemmBlocks = (n + 127) / 128;
    int aggBlocks  = (n + 31) / 32;

    uint4* thA; cudaGetSymbolAddress((void**)&thA, g_thA);
    uint4* thB; cudaGetSymbolAddress((void**)&thB, g_thB);

    // layer 1: GEMM on x -> thA
    k_gemm1<<<gemmBlocks, 256>>>(x, W1, n);
    // layer 2: fused agg(thA) + relu(+b1) + GEMM(W2) -> thB
    k_fused<<<gemmBlocks, 256>>>(thA, thB, W2, b1, n);
    // layer 3: fused agg(thB) + relu(+b2) + GEMM(W3) -> thA
    k_fused<<<gemmBlocks, 256>>>(thB, thA, W3, b2, n);
    // final aggregation of layer-3 messages
    k_agg<<<aggBlocks, 256>>>(thA, n);

    // pool (bias+relu of layer 3 fused) + final linear
    k_pool<<<(n + 255) / 256, 256>>>(batch, b3, n);
    k_final<<<1, NGR>>>(lw, lb, out);
}